// round 7
// baseline (speedup 1.0000x reference)
#include <cuda_runtime.h>

#define NB   2
#define CDIM 64
#define MDIM 4800
#define KDIM 64
#define EPSV 1e-5f

// ---------------- device scratch (no allocations allowed) ----------------
__device__ float d_S0s[NB * CDIM * KDIM];   // s0-scaled scene part of layer0, [n][c][k]
__device__ float d_A1s[NB * CDIM * KDIM];   // s1a*(W1a_xyz @ sx) + t1a,      [n][c][k]
__device__ float d_Ask[NB * CDIM * KDIM];   // Wskip_xyz @ sx,                [n][c][k]
__device__ float d_W1aT[CDIM * CDIM];       // s1a[c]*W1a[c][j] stored [j][c]
__device__ float d_W1bT[CDIM * CDIM];       // s1b[c]*W1b[c][j] stored [j][c]
__device__ float d_WskT[CDIM * CDIM];       // Wskip[c][j]      stored [j][c]
__device__ float d_s0v[CDIM];
__device__ float d_t0v[CDIM];
__device__ float d_t1bv[CDIM];
__device__ float d_q0[NB * MDIM * CDIM];    // per-m folded query vector, [gm][c]

// ---------------- packed fp32x2 helpers ----------------
// fma.rn.f32x2 is sm_100+ PTX; fall back to two scalar rn-FMAs elsewhere
// (bitwise-identical results — the packed op IS two independent rn FMAs).
__device__ __forceinline__ void ffma2(unsigned long long& d,
                                      unsigned long long a,
                                      unsigned long long b)
{
#if !defined(__CUDA_ARCH__) || (__CUDA_ARCH__ >= 1000)
    asm("fma.rn.f32x2 %0, %1, %2, %0;" : "+l"(d) : "l"(a), "l"(b));
#else
    float dl = __uint_as_float((unsigned)d);
    float dh = __uint_as_float((unsigned)(d >> 32));
    dl = fmaf(__uint_as_float((unsigned)a), __uint_as_float((unsigned)b), dl);
    dh = fmaf(__uint_as_float((unsigned)(a >> 32)),
              __uint_as_float((unsigned)(b >> 32)), dh);
    d = ((unsigned long long)__float_as_uint(dh) << 32) | __float_as_uint(dl);
#endif
}
__device__ __forceinline__ float lo2(unsigned long long v)
{
    return __uint_as_float((unsigned)v);
}
__device__ __forceinline__ float hi2(unsigned long long v)
{
    return __uint_as_float((unsigned)(v >> 32));
}

// ---------------- precompute: BN folding + m-independent planes ----------------
__global__ void prep_kernel(
    const float* __restrict__ srgb,   // (2,64,1,64)
    const float* __restrict__ sxyz,   // (2,3,1,64)
    const float* __restrict__ maskp,  // (2,1,1,64)
    const float* __restrict__ W0,     // (64,128)
    const float* __restrict__ g0, const float* __restrict__ b0,
    const float* __restrict__ m0, const float* __restrict__ v0,
    const float* __restrict__ W1a,    // (64,67)
    const float* __restrict__ g1a, const float* __restrict__ b1a,
    const float* __restrict__ m1a, const float* __restrict__ v1a,
    const float* __restrict__ W1b,    // (64,64)
    const float* __restrict__ g1b, const float* __restrict__ b1b,
    const float* __restrict__ m1b, const float* __restrict__ v1b,
    const float* __restrict__ Wsk)    // (64,67)
{
    __shared__ float s_s0[64], s_s1a[64], s_t1a[64], s_s1b[64];
    int tid = threadIdx.x;
    if (tid < 64) {
        float s = g0[tid] * rsqrtf(v0[tid] + EPSV);
        s_s0[tid] = s;
        d_s0v[tid] = s;
        d_t0v[tid] = b0[tid] - m0[tid] * s;
        float sa = g1a[tid] * rsqrtf(v1a[tid] + EPSV);
        s_s1a[tid] = sa;
        s_t1a[tid] = b1a[tid] - m1a[tid] * sa;
        float sb = g1b[tid] * rsqrtf(v1b[tid] + EPSV);
        s_s1b[tid] = sb;
        d_t1bv[tid] = b1b[tid] - m1b[tid] * sb;
    }
    __syncthreads();

    // transposed, BN-scaled weights
    for (int idx = tid; idx < 4096; idx += 256) {
        int j = idx >> 6, c = idx & 63;
        d_W1aT[idx] = s_s1a[c] * W1a[c * 67 + j];
        d_W1bT[idx] = s_s1b[c] * W1b[c * 64 + j];
        d_WskT[idx] = Wsk[c * 67 + j];
    }

    // per-(n,c,k) planes
    for (int idx = tid; idx < NB * CDIM * KDIM; idx += 256) {
        int n = idx >> 12, c = (idx >> 6) & 63, k = idx & 63;
        // scene part of layer0
        float acc = 0.f;
        const float* w = W0 + c * 128;
        const float* s = srgb + n * 4096 + k;
        #pragma unroll 8
        for (int j = 0; j < 64; j++) acc = fmaf(w[j], s[j * 64], acc);
        d_S0s[idx] = s_s0[c] * acc;
        // masked xyz contributions
        float mk = maskp[n * 64 + k];
        float x0 = sxyz[n * 192 +   0 + k] * mk;
        float x1 = sxyz[n * 192 +  64 + k] * mk;
        float x2 = sxyz[n * 192 + 128 + k] * mk;
        const float* wa = W1a + c * 67 + 64;
        const float* ws = Wsk + c * 67 + 64;
        d_A1s[idx] = s_s1a[c] * (wa[0] * x0 + wa[1] * x1 + wa[2] * x2) + s_t1a[c];
        d_Ask[idx] = ws[0] * x0 + ws[1] * x1 + ws[2] * x2;
    }
}

// ---------------- q0[gm][c] = s0[c]*(W0q @ query[:,m]) + t0[c] ----------------
__global__ void q0_kernel(const float* __restrict__ query,  // (2,64,4800,1)
                          const float* __restrict__ W0)     // (64,128)
{
    __shared__ float sW[4096];     // [j][c]
    __shared__ float sQ[64 * 16];  // [j][ml]
    int b = blockIdx.x;            // 600 blocks, 16 m each (never crosses n)
    int gm0 = b * 16;
    int n = gm0 / MDIM;
    int mstart = gm0 - n * MDIM;
    int tid = threadIdx.x;

    for (int idx = tid; idx < 4096; idx += 256) {
        int j = idx >> 6, c = idx & 63;
        sW[idx] = W0[c * 128 + 64 + j];
    }
    for (int idx = tid; idx < 1024; idx += 256) {
        int j = idx >> 4, ml = idx & 15;
        sQ[idx] = query[n * (64 * MDIM) + j * MDIM + mstart + ml];
    }
    __syncthreads();

    int c = tid & 63, grp = tid >> 6;
    float s0c = d_s0v[c], t0c = d_t0v[c];
    #pragma unroll
    for (int mi = 0; mi < 4; mi++) {
        int ml = grp * 4 + mi;
        float acc = 0.f;
        #pragma unroll 16
        for (int j = 0; j < 64; j++) acc = fmaf(sW[j * 64 + c], sQ[j * 16 + ml], acc);
        d_q0[(gm0 + ml) * 64 + c] = fmaf(s0c, acc, t0c);
    }
}

// ---------------- main fused kernel ----------------
// smem layout (floats). Activation tiles (H, H1) are stored DUPLICATED:
// row j holds [h0,h0,h1,h1,...,h7,h7] (16 floats) so the {h,h} broadcast
// operand for fma.rn.f32x2 is a direct LDS.128 (zero packing MOVs).
//
// sS0 uses stride 72 (8 mod 32): h-gen footprint (4 consecutive j) x (8 k)
// maps to banks (8j+k) mod 32 = conflict-free permutation.
// sA1/sAs keep stride 65: their epilogue reads are indexed by c*stride with
// even c, where stride 72 would collapse to 16-way conflicts.
#define S0STR   72
#define OFF_S0  0
#define OFF_A1  (OFF_S0 + NB * 64 * S0STR)
#define OFF_AS  (OFF_A1 + NB * 64 * 65)
#define OFF_WA  (OFF_AS + NB * 64 * 65)
#define OFF_WB  (OFF_WA + 4096)
#define OFF_WS  (OFF_WB + 4096)
#define OFF_T1B (OFF_WS + 4096)
#define OFF_WO  (OFF_T1B + 64)
#define OFF_Q0  (OFF_WO + 208)
#define OFF_H   (OFF_Q0 + 8 * 64)
#define OFF_H1  (OFF_H + 8 * 1024)
#define SMEM_FLOATS (OFF_H1 + 8 * 1024)        // 55312 floats = 221,248 B

// One j-step of matvec2: 4c x 4k outer product, channels packed 2-wide.
__device__ __forceinline__ void mv2_step(const float* __restrict__ W,
                                         const float* __restrict__ H2,
                                         int j, int cbase, int kgrp,
                                         unsigned long long acc[2][4])
{
    ulonglong2 w2 = *(const ulonglong2*)(W + j * 64 + cbase);          // {w0,w1},{w2,w3}
    ulonglong2 hA = *(const ulonglong2*)(H2 + j * 16 + kgrp * 2);      // {h0,h0},{h1,h1}
    ulonglong2 hB = *(const ulonglong2*)(H2 + j * 16 + kgrp * 2 + 4);  // {h2,h2},{h3,h3}
    ffma2(acc[0][0], w2.x, hA.x);
    ffma2(acc[1][0], w2.y, hA.x);
    ffma2(acc[0][1], w2.x, hA.y);
    ffma2(acc[1][1], w2.y, hA.y);
    ffma2(acc[0][2], w2.x, hB.x);
    ffma2(acc[1][2], w2.y, hB.x);
    ffma2(acc[0][3], w2.x, hB.y);
    ffma2(acc[1][3], w2.y, hB.y);
}

// One j-step of merged matvec1 + matvec3: both read the same h operands
// (2 shared LDS.128) against two weight matrices (2 LDS.128) -> 16 FFMA2.
__device__ __forceinline__ void mv2_step_dual(const float* __restrict__ Wa,
                                              const float* __restrict__ Ws,
                                              const float* __restrict__ H2,
                                              int j, int cbase, int kgrp,
                                              unsigned long long acc1[2][4],
                                              unsigned long long acc3[2][4])
{
    ulonglong2 wa = *(const ulonglong2*)(Wa + j * 64 + cbase);
    ulonglong2 ws = *(const ulonglong2*)(Ws + j * 64 + cbase);
    ulonglong2 hA = *(const ulonglong2*)(H2 + j * 16 + kgrp * 2);
    ulonglong2 hB = *(const ulonglong2*)(H2 + j * 16 + kgrp * 2 + 4);
    ffma2(acc1[0][0], wa.x, hA.x);
    ffma2(acc1[1][0], wa.y, hA.x);
    ffma2(acc1[0][1], wa.x, hA.y);
    ffma2(acc1[1][1], wa.y, hA.y);
    ffma2(acc1[0][2], wa.x, hB.x);
    ffma2(acc1[1][2], wa.y, hB.x);
    ffma2(acc1[0][3], wa.x, hB.y);
    ffma2(acc1[1][3], wa.y, hB.y);
    ffma2(acc3[0][0], ws.x, hA.x);
    ffma2(acc3[1][0], ws.y, hA.x);
    ffma2(acc3[0][1], ws.x, hA.y);
    ffma2(acc3[1][1], ws.y, hA.y);
    ffma2(acc3[0][2], ws.x, hB.x);
    ffma2(acc3[1][2], ws.y, hB.x);
    ffma2(acc3[0][3], ws.x, hB.y);
    ffma2(acc3[1][3], ws.y, hB.y);
}

__global__ void __launch_bounds__(256, 1)
main_kernel(const float* __restrict__ prexyz,  // (2,3,4800)
            const float* __restrict__ Wout,    // (3,67)
            float* __restrict__ out)           // (2,3,4800)
{
    extern __shared__ float sm[];
    float* sS0  = sm + OFF_S0;
    float* sA1  = sm + OFF_A1;
    float* sAs  = sm + OFF_AS;
    float* sWa  = sm + OFF_WA;
    float* sWb  = sm + OFF_WB;
    float* sWs  = sm + OFF_WS;
    float* sT1b = sm + OFF_T1B;
    float* sWo  = sm + OFF_WO;
    float* sQ0  = sm + OFF_Q0;
    float* sH   = sm + OFF_H;
    float* sH1  = sm + OFF_H1;

    int tid = threadIdx.x;
    for (int idx = tid; idx < NB * CDIM * KDIM; idx += 256) {
        int nc = idx >> 6, k = idx & 63;
        sS0[nc * S0STR + k] = d_S0s[idx];
        sA1[nc * 65 + k] = d_A1s[idx];
        sAs[nc * 65 + k] = d_Ask[idx];
    }
    for (int idx = tid; idx < 4096; idx += 256) {
        sWa[idx] = d_W1aT[idx];
        sWb[idx] = d_W1bT[idx];
        sWs[idx] = d_WskT[idx];
    }
    if (tid < 64) sT1b[tid] = d_t1bv[tid];
    for (int idx = tid; idx < 201; idx += 256) sWo[idx] = Wout[idx];
    __syncthreads();

    int wid = tid >> 5, lane = tid & 31;
    int flatW = blockIdx.x * 8 + wid;          // 0..1183
    float* myH  = sH  + wid * 1024;            // duplicated layout: j*16 + 2k {v,v}
    float* myH1 = sH1 + wid * 1024;
    float* myQ0 = sQ0 + wid * 64;
    const int cbase = (lane & 15) * 4;         // channel rows owned by lane
    const int kgrp  = (lane >> 4) * 4;         // k sub-group within 8-wide chunk

    // software prefetch of q0 for the first m-round
    float q0lo = 0.f, q0hi = 0.f;
    if (flatW < NB * MDIM) {
        q0lo = d_q0[flatW * 64 + lane];
        q0hi = d_q0[flatW * 64 + lane + 32];
    }

    for (int gm = flatW; gm < NB * MDIM; gm += 1184) {
        int n = gm >= MDIM;
        int m = gm - n * MDIM;
        const float* nS0 = sS0 + n * (64 * S0STR);
        const float* nA1 = sA1 + n * (64 * 65);
        const float* nAs = sAs + n * (64 * 65);

        // stage prefetched q0 vector for this m, then start next round's load
        myQ0[lane]      = q0lo;
        myQ0[lane + 32] = q0hi;
        __syncwarp();
        int gmn = gm + 1184;
        if (gmn < NB * MDIM) {
            q0lo = d_q0[gmn * 64 + lane];      // overlaps with compute below
            q0hi = d_q0[gmn * 64 + lane + 32];
        }

        float mx[4] = {-1e30f, -1e30f, -1e30f, -1e30f};

        for (int kc = 0; kc < KDIM; kc += 8) {
            // ---- generate h = relu(S0s + q0), stored duplicated ----
            #pragma unroll
            for (int r = 0; r < 16; r++) {
                int flat = r * 32 + lane;
                int j = flat >> 3, k8 = flat & 7;
                float v = fmaxf(nS0[j * S0STR + kc + k8] + myQ0[j], 0.f);
                *(float2*)(myH + j * 16 + k8 * 2) = make_float2(v, v);
            }
            __syncwarp();

            // ---- merged matvec1 (W1as @ h) + matvec3 (Wskip0 @ h) ----
            unsigned long long acc[2][4], acc3[2][4];
            #pragma unroll
            for (int p = 0; p < 2; p++)
                #pragma unroll
                for (int kk = 0; kk < 4; kk++) { acc[p][kk] = 0ull; acc3[p][kk] = 0ull; }
            #pragma unroll 8
            for (int j = 0; j < 64; j++)
                mv2_step_dual(sWa, sWs, myH, j, cbase, kgrp, acc, acc3);

            // h1a = relu(acc + A1s) -> duplicated smem
            #pragma unroll
            for (int p = 0; p < 2; p++) {
                #pragma unroll
                for (int half = 0; half < 2; half++) {
                    int c = cbase + 2 * p + half;
                    const float* biasA = nA1 + c * 65 + kc + kgrp;
                    float o0, o1, o2, o3;
                    if (half == 0) {
                        o0 = lo2(acc[p][0]); o1 = lo2(acc[p][1]);
                        o2 = lo2(acc[p][2]); o3 = lo2(acc[p][3]);
                    } else {
                        o0 = hi2(acc[p][0]); o1 = hi2(acc[p][1]);
                        o2 = hi2(acc[p][2]); o3 = hi2(acc[p][3]);
                    }
                    o0 = fmaxf(o0 + biasA[0], 0.f);
                    o1 = fmaxf(o1 + biasA[1], 0.f);
                    o2 = fmaxf(o2 + biasA[2], 0.f);
                    o3 = fmaxf(o3 + biasA[3], 0.f);
                    *(float4*)(myH1 + c * 16 + kgrp * 2)     = make_float4(o0, o0, o1, o1);
                    *(float4*)(myH1 + c * 16 + kgrp * 2 + 4) = make_float4(o2, o2, o3, o3);
                }
            }
            __syncwarp();

            // ---- matvec2: h1b = W1bs @ h1a (bias+relu deferred) ----
            unsigned long long h1b[2][4];
            #pragma unroll
            for (int p = 0; p < 2; p++)
                #pragma unroll
                for (int kk = 0; kk < 4; kk++) h1b[p][kk] = 0ull;
            #pragma unroll 8
            for (int j = 0; j < 64; j++) mv2_step(sWb, myH1, j, cbase, kgrp, h1b);

            // ---- feat = relu(h1b + t1b) + skip + Askip ; running max over k ----
            #pragma unroll
            for (int p = 0; p < 2; p++) {
                #pragma unroll
                for (int half = 0; half < 2; half++) {
                    int c = cbase + 2 * p + half;
                    float t = sT1b[c];
                    const float* biasS = nAs + c * 65 + kc + kgrp;
                    #pragma unroll
                    for (int kk = 0; kk < 4; kk++) {
                        float hb = half ? hi2(h1b[p][kk]) : lo2(h1b[p][kk]);
                        float sk = half ? hi2(acc3[p][kk]) : lo2(acc3[p][kk]);
                        float fp = fmaxf(hb + t, 0.f) + sk + biasS[kk];
                        mx[2 * p + half] = fmaxf(mx[2 * p + half], fp);
                    }
                }
            }
            __syncwarp();   // protect myH/myH1 before next chunk rewrites them
        }

        // combine the two k-halves of the warp
        #pragma unroll
        for (int cc = 0; cc < 4; cc++)
            mx[cc] = fmaxf(mx[cc], __shfl_xor_sync(0xffffffffu, mx[cc], 16));

        // out = Wout[:, :64] @ feat  (+ xyz terms), via shuffle reduction
        float p0 = 0.f, p1 = 0.f, p2 = 0.f;
        if (lane < 16) {
            #pragma unroll
            for (int cc = 0; cc < 4; cc++) {
                int c = cbase + cc;
                float f = mx[cc];
                p0 = fmaf(sWo[c],       f, p0);
                p1 = fmaf(sWo[67 + c],  f, p1);
                p2 = fmaf(sWo[134 + c], f, p2);
            }
        }
        #pragma unroll
        for (int off = 8; off >= 1; off >>= 1) {
            p0 += __shfl_xor_sync(0xffffffffu, p0, off);
            p1 += __shfl_xor_sync(0xffffffffu, p1, off);
            p2 += __shfl_xor_sync(0xffffffffu, p2, off);
        }
        if (lane == 0) {
            float px = prexyz[n * 14400 +        m];
            float py = prexyz[n * 14400 + 4800 + m];
            float pz = prexyz[n * 14400 + 9600 + m];
            out[(n * 3 + 0) * MDIM + m] = p0 + sWo[64]  * px + sWo[65]  * py + sWo[66]  * pz;
            out[(n * 3 + 1) * MDIM + m] = p1 + sWo[131] * px + sWo[132] * py + sWo[133] * pz;
            out[(n * 3 + 2) * MDIM + m] = p2 + sWo[198] * px + sWo[199] * py + sWo[200] * pz;
        }
    }
}

// ---------------- launcher ----------------
extern "C" void kernel_launch(void* const* d_in, const int* in_sizes, int n_in,
                              void* d_out, int out_size)
{
    const float* query = (const float*)d_in[0];
    const float* srgb  = (const float*)d_in[1];
    const float* sxyz  = (const float*)d_in[2];
    const float* prex  = (const float*)d_in[3];
    const float* maskp = (const float*)d_in[4];
    const float* W0    = (const float*)d_in[5];
    const float* g0    = (const float*)d_in[6];
    const float* b0    = (const float*)d_in[7];
    const float* m0    = (const float*)d_in[8];
    const float* v0    = (const float*)d_in[9];
    const float* W1a   = (const float*)d_in[10];
    const float* g1a   = (const float*)d_in[11];
    const float* b1a   = (const float*)d_in[12];
    const float* m1a   = (const float*)d_in[13];
    const float* v1a   = (const float*)d_in[14];
    const float* W1b   = (const float*)d_in[15];
    const float* g1b   = (const float*)d_in[16];
    const float* b1b   = (const float*)d_in[17];
    const float* m1b   = (const float*)d_in[18];
    const float* v1b   = (const float*)d_in[19];
    const float* Wsk   = (const float*)d_in[20];
    const float* Wout  = (const float*)d_in[21];
    float* out = (float*)d_out;

    prep_kernel<<<1, 256>>>(srgb, sxyz, maskp, W0,
                            g0, b0, m0, v0,
                            W1a, g1a, b1a, m1a, v1a,
                            W1b, g1b, b1b, m1b, v1b,
                            Wsk);
    q0_kernel<<<600, 256>>>(query, W0);

    const size_t smem_bytes = SMEM_FLOATS * sizeof(float);  // ~216 KB
    cudaFuncSetAttribute(main_kernel, cudaFuncAttributeMaxDynamicSharedMemorySize,
                         (int)smem_bytes);
    main_kernel<<<148, 256, smem_bytes>>>(prex, Wout, out);
}

// round 17
// speedup vs baseline: 1.1684x; 1.1684x over previous
#include <cuda_runtime.h>

#define NB   2
#define CDIM 64
#define MDIM 4800
#define KDIM 64
#define EPSV 1e-5f
#define NPLANE (NB * CDIM * KDIM)   // 8192 — plane entry count (NOT 16384!)

// ---------------- device scratch (no allocations allowed) ----------------
__device__ float d_S0s[NPLANE];             // s0-scaled scene part of layer0, [n][c][k]
__device__ float d_A1s[NPLANE];             // s1a*(W1a_xyz @ sx) + t1a,      [n][c][k]
__device__ float d_Ask[NPLANE];             // Wskip_xyz @ sx,                [n][c][k]
__device__ float d_W1aT[CDIM * CDIM];       // s1a[c]*W1a[c][j] stored [j][c]
__device__ float d_W1bT[CDIM * CDIM];       // s1b[c]*W1b[c][j] stored [j][c]
__device__ float d_WskT[CDIM * CDIM];       // Wskip[c][j]      stored [j][c]
__device__ float d_s0v[CDIM];
__device__ float d_t0v[CDIM];
__device__ float d_t1bv[CDIM];
__device__ float d_q0[NB * MDIM * CDIM];    // per-m folded query vector, [gm][c]

// ---------------- packed fp32x2 helpers ----------------
__device__ __forceinline__ void ffma2(unsigned long long& d,
                                      unsigned long long a,
                                      unsigned long long b)
{
#if !defined(__CUDA_ARCH__) || (__CUDA_ARCH__ >= 1000)
    asm("fma.rn.f32x2 %0, %1, %2, %0;" : "+l"(d) : "l"(a), "l"(b));
#else
    float dl = __uint_as_float((unsigned)d);
    float dh = __uint_as_float((unsigned)(d >> 32));
    dl = fmaf(__uint_as_float((unsigned)a), __uint_as_float((unsigned)b), dl);
    dh = fmaf(__uint_as_float((unsigned)(a >> 32)),
              __uint_as_float((unsigned)(b >> 32)), dh);
    d = ((unsigned long long)__float_as_uint(dh) << 32) | __float_as_uint(dl);
#endif
}
__device__ __forceinline__ float lo2(unsigned long long v)
{
    return __uint_as_float((unsigned)v);
}
__device__ __forceinline__ float hi2(unsigned long long v)
{
    return __uint_as_float((unsigned)(v >> 32));
}

// ---------------- precompute: BN folding + m-independent planes ----------------
// 32 blocks x 256 threads = exactly NPLANE (8192) plane entries, one per thread.
// (Round-16 failure root cause: 64 blocks wrote idx up to 16383 into 8192-entry
// arrays, overflowing d_S0s into d_A1s/d_Ask/d_W1aT. Guard added so the grid
// constant can never silently diverge from the array size again.)
__global__ void prep_kernel(
    const float* __restrict__ srgb,   // (2,64,1,64)
    const float* __restrict__ sxyz,   // (2,3,1,64)
    const float* __restrict__ maskp,  // (2,1,1,64)
    const float* __restrict__ W0,     // (64,128)
    const float* __restrict__ g0, const float* __restrict__ b0,
    const float* __restrict__ m0, const float* __restrict__ v0,
    const float* __restrict__ W1a,    // (64,67)
    const float* __restrict__ g1a, const float* __restrict__ b1a,
    const float* __restrict__ m1a, const float* __restrict__ v1a,
    const float* __restrict__ W1b,    // (64,64)
    const float* __restrict__ g1b, const float* __restrict__ b1b,
    const float* __restrict__ m1b, const float* __restrict__ v1b,
    const float* __restrict__ Wsk)    // (64,67)
{
    __shared__ float s_s0[64], s_s1a[64], s_t1a[64], s_s1b[64];
    int tid = threadIdx.x;
    int bid = blockIdx.x;
    if (tid < 64) {
        float s = g0[tid] * rsqrtf(v0[tid] + EPSV);
        s_s0[tid] = s;
        float sa = g1a[tid] * rsqrtf(v1a[tid] + EPSV);
        s_s1a[tid] = sa;
        s_t1a[tid] = b1a[tid] - m1a[tid] * sa;
        float sb = g1b[tid] * rsqrtf(v1b[tid] + EPSV);
        s_s1b[tid] = sb;
        if (bid == 0) {
            d_s0v[tid] = s;
            d_t0v[tid] = b0[tid] - m0[tid] * s;
            d_t1bv[tid] = b1b[tid] - m1b[tid] * sb;
        }
    }
    __syncthreads();

    // transposed, BN-scaled weights (block 0 only)
    if (bid == 0) {
        for (int idx = tid; idx < 4096; idx += 256) {
            int j = idx >> 6, c = idx & 63;
            d_W1aT[idx] = s_s1a[c] * W1a[c * 67 + j];
            d_W1bT[idx] = s_s1b[c] * W1b[c * 64 + j];
            d_WskT[idx] = Wsk[c * 67 + j];
        }
    }

    // per-(n,c,k) planes: one entry per thread, bounds-guarded
    {
        int idx = bid * 256 + tid;
        if (idx < NPLANE) {
            int n = idx >> 12, c = (idx >> 6) & 63, k = idx & 63;
            float acc = 0.f;
            const float* w = W0 + c * 128;
            const float* s = srgb + n * 4096 + k;
            #pragma unroll 8
            for (int j = 0; j < 64; j++) acc = fmaf(w[j], s[j * 64], acc);
            d_S0s[idx] = s_s0[c] * acc;
            float mk = maskp[n * 64 + k];
            float x0 = sxyz[n * 192 +   0 + k] * mk;
            float x1 = sxyz[n * 192 +  64 + k] * mk;
            float x2 = sxyz[n * 192 + 128 + k] * mk;
            const float* wa = W1a + c * 67 + 64;
            const float* ws = Wsk + c * 67 + 64;
            d_A1s[idx] = s_s1a[c] * (wa[0] * x0 + wa[1] * x1 + wa[2] * x2) + s_t1a[c];
            d_Ask[idx] = ws[0] * x0 + ws[1] * x1 + ws[2] * x2;
        }
    }
}

// ---------------- q0[gm][c] = s0[c]*(W0q @ query[:,m]) + t0[c] ----------------
__global__ void q0_kernel(const float* __restrict__ query,  // (2,64,4800,1)
                          const float* __restrict__ W0)     // (64,128)
{
    __shared__ float sW[4096];     // [j][c]
    __shared__ float sQ[64 * 16];  // [j][ml]
    int b = blockIdx.x;            // 600 blocks, 16 m each (never crosses n)
    int gm0 = b * 16;
    int n = gm0 / MDIM;
    int mstart = gm0 - n * MDIM;
    int tid = threadIdx.x;

    for (int idx = tid; idx < 4096; idx += 256) {
        int j = idx >> 6, c = idx & 63;
        sW[idx] = W0[c * 128 + 64 + j];
    }
    for (int idx = tid; idx < 1024; idx += 256) {
        int j = idx >> 4, ml = idx & 15;
        sQ[idx] = query[n * (64 * MDIM) + j * MDIM + mstart + ml];
    }
    __syncthreads();

    int c = tid & 63, grp = tid >> 6;
    float s0c = d_s0v[c], t0c = d_t0v[c];
    #pragma unroll
    for (int mi = 0; mi < 4; mi++) {
        int ml = grp * 4 + mi;
        float acc = 0.f;
        #pragma unroll 16
        for (int j = 0; j < 64; j++) acc = fmaf(sW[j * 64 + c], sQ[j * 16 + ml], acc);
        d_q0[(gm0 + ml) * 64 + c] = fmaf(s0c, acc, t0c);
    }
}

// ---------------- main fused kernel ----------------
#define S0STR   72
#define OFF_S0  0
#define OFF_A1  (OFF_S0 + NB * 64 * S0STR)
#define OFF_AS  (OFF_A1 + NB * 64 * 65)
#define OFF_WA  (OFF_AS + NB * 64 * 65)
#define OFF_WB  (OFF_WA + 4096)
#define OFF_WS  (OFF_WB + 4096)
#define OFF_T1B (OFF_WS + 4096)
#define OFF_WO  (OFF_T1B + 64)
#define OFF_Q0  (OFF_WO + 208)
#define OFF_H   (OFF_Q0 + 8 * 64)
#define OFF_H1  (OFF_H + 8 * 1024)
#define OFF_TL  (OFF_H1 + 8 * 1024)            // tail reduce buffer 8x64
#define SMEM_FLOATS (OFF_TL + 512)             // 55824 floats = 223,296 B

__device__ __forceinline__ void mv2_step(const float* __restrict__ W,
                                         const float* __restrict__ H2,
                                         int j, int cbase, int kgrp,
                                         unsigned long long acc[2][4])
{
    ulonglong2 w2 = *(const ulonglong2*)(W + j * 64 + cbase);
    ulonglong2 hA = *(const ulonglong2*)(H2 + j * 16 + kgrp * 2);
    ulonglong2 hB = *(const ulonglong2*)(H2 + j * 16 + kgrp * 2 + 4);
    ffma2(acc[0][0], w2.x, hA.x);
    ffma2(acc[1][0], w2.y, hA.x);
    ffma2(acc[0][1], w2.x, hA.y);
    ffma2(acc[1][1], w2.y, hA.y);
    ffma2(acc[0][2], w2.x, hB.x);
    ffma2(acc[1][2], w2.y, hB.x);
    ffma2(acc[0][3], w2.x, hB.y);
    ffma2(acc[1][3], w2.y, hB.y);
}

__device__ __forceinline__ void mv2_step_dual(const float* __restrict__ Wa,
                                              const float* __restrict__ Ws,
                                              const float* __restrict__ H2,
                                              int j, int cbase, int kgrp,
                                              unsigned long long acc1[2][4],
                                              unsigned long long acc3[2][4])
{
    ulonglong2 wa = *(const ulonglong2*)(Wa + j * 64 + cbase);
    ulonglong2 ws = *(const ulonglong2*)(Ws + j * 64 + cbase);
    ulonglong2 hA = *(const ulonglong2*)(H2 + j * 16 + kgrp * 2);
    ulonglong2 hB = *(const ulonglong2*)(H2 + j * 16 + kgrp * 2 + 4);
    ffma2(acc1[0][0], wa.x, hA.x);
    ffma2(acc1[1][0], wa.y, hA.x);
    ffma2(acc1[0][1], wa.x, hA.y);
    ffma2(acc1[1][1], wa.y, hA.y);
    ffma2(acc1[0][2], wa.x, hB.x);
    ffma2(acc1[1][2], wa.y, hB.x);
    ffma2(acc1[0][3], wa.x, hB.y);
    ffma2(acc1[1][3], wa.y, hB.y);
    ffma2(acc3[0][0], ws.x, hA.x);
    ffma2(acc3[1][0], ws.y, hA.x);
    ffma2(acc3[0][1], ws.x, hA.y);
    ffma2(acc3[1][1], ws.y, hA.y);
    ffma2(acc3[0][2], ws.x, hB.x);
    ffma2(acc3[1][2], ws.y, hB.x);
    ffma2(acc3[0][3], ws.x, hB.y);
    ffma2(acc3[1][3], ws.y, hB.y);
}

// One 8-k chunk of the three-matvec pipeline; updates mx[4] (channel maxes).
__device__ __forceinline__ void chunk_body(const float* __restrict__ nS0,
                                           const float* __restrict__ nA1,
                                           const float* __restrict__ nAs,
                                           const float* __restrict__ sWa,
                                           const float* __restrict__ sWb,
                                           const float* __restrict__ sWs,
                                           const float* __restrict__ sT1b,
                                           float* __restrict__ myH,
                                           float* __restrict__ myH1,
                                           const float* __restrict__ myQ0,
                                           int kc, int lane, int cbase, int kgrp,
                                           float mx[4])
{
    // ---- generate h = relu(S0s + q0), stored duplicated ----
    #pragma unroll
    for (int r = 0; r < 16; r++) {
        int flat = r * 32 + lane;
        int j = flat >> 3, k8 = flat & 7;
        float v = fmaxf(nS0[j * S0STR + kc + k8] + myQ0[j], 0.f);
        *(float2*)(myH + j * 16 + k8 * 2) = make_float2(v, v);
    }
    __syncwarp();

    // ---- merged matvec1 (W1as @ h) + matvec3 (Wskip0 @ h) ----
    unsigned long long acc[2][4], acc3[2][4];
    #pragma unroll
    for (int p = 0; p < 2; p++)
        #pragma unroll
        for (int kk = 0; kk < 4; kk++) { acc[p][kk] = 0ull; acc3[p][kk] = 0ull; }
    #pragma unroll 8
    for (int j = 0; j < 64; j++)
        mv2_step_dual(sWa, sWs, myH, j, cbase, kgrp, acc, acc3);

    // h1a = relu(acc + A1s) -> duplicated smem
    #pragma unroll
    for (int p = 0; p < 2; p++) {
        #pragma unroll
        for (int half = 0; half < 2; half++) {
            int c = cbase + 2 * p + half;
            const float* biasA = nA1 + c * 65 + kc + kgrp;
            float o0, o1, o2, o3;
            if (half == 0) {
                o0 = lo2(acc[p][0]); o1 = lo2(acc[p][1]);
                o2 = lo2(acc[p][2]); o3 = lo2(acc[p][3]);
            } else {
                o0 = hi2(acc[p][0]); o1 = hi2(acc[p][1]);
                o2 = hi2(acc[p][2]); o3 = hi2(acc[p][3]);
            }
            o0 = fmaxf(o0 + biasA[0], 0.f);
            o1 = fmaxf(o1 + biasA[1], 0.f);
            o2 = fmaxf(o2 + biasA[2], 0.f);
            o3 = fmaxf(o3 + biasA[3], 0.f);
            *(float4*)(myH1 + c * 16 + kgrp * 2)     = make_float4(o0, o0, o1, o1);
            *(float4*)(myH1 + c * 16 + kgrp * 2 + 4) = make_float4(o2, o2, o3, o3);
        }
    }
    __syncwarp();

    // ---- matvec2: h1b = W1bs @ h1a ----
    unsigned long long h1b[2][4];
    #pragma unroll
    for (int p = 0; p < 2; p++)
        #pragma unroll
        for (int kk = 0; kk < 4; kk++) h1b[p][kk] = 0ull;
    #pragma unroll 8
    for (int j = 0; j < 64; j++) mv2_step(sWb, myH1, j, cbase, kgrp, h1b);

    // ---- feat = relu(h1b + t1b) + skip + Askip ; running max over k ----
    #pragma unroll
    for (int p = 0; p < 2; p++) {
        #pragma unroll
        for (int half = 0; half < 2; half++) {
            int c = cbase + 2 * p + half;
            float t = sT1b[c];
            const float* biasS = nAs + c * 65 + kc + kgrp;
            #pragma unroll
            for (int kk = 0; kk < 4; kk++) {
                float hb = half ? hi2(h1b[p][kk]) : lo2(h1b[p][kk]);
                float sk = half ? hi2(acc3[p][kk]) : lo2(acc3[p][kk]);
                float fp = fmaxf(hb + t, 0.f) + sk + biasS[kk];
                mx[2 * p + half] = fmaxf(mx[2 * p + half], fp);
            }
        }
    }
    __syncwarp();   // protect myH/myH1 before next chunk rewrites them
}

// Epilogue: project feat (lanes 0..15 hold mx for 4 channels each) + xyz, store.
__device__ __forceinline__ void project_store(const float* __restrict__ sWo,
                                              const float* __restrict__ prexyz,
                                              float* __restrict__ out,
                                              const float mx[4],
                                              int lane, int cbase, int n, int m)
{
    float p0 = 0.f, p1 = 0.f, p2 = 0.f;
    if (lane < 16) {
        #pragma unroll
        for (int cc = 0; cc < 4; cc++) {
            int c = cbase + cc;
            float f = mx[cc];
            p0 = fmaf(sWo[c],       f, p0);
            p1 = fmaf(sWo[67 + c],  f, p1);
            p2 = fmaf(sWo[134 + c], f, p2);
        }
    }
    #pragma unroll
    for (int off = 8; off >= 1; off >>= 1) {
        p0 += __shfl_xor_sync(0xffffffffu, p0, off);
        p1 += __shfl_xor_sync(0xffffffffu, p1, off);
        p2 += __shfl_xor_sync(0xffffffffu, p2, off);
    }
    if (lane == 0) {
        float px = prexyz[n * 14400 +        m];
        float py = prexyz[n * 14400 + 4800 + m];
        float pz = prexyz[n * 14400 + 9600 + m];
        out[(n * 3 + 0) * MDIM + m] = p0 + sWo[64]  * px + sWo[65]  * py + sWo[66]  * pz;
        out[(n * 3 + 1) * MDIM + m] = p1 + sWo[131] * px + sWo[132] * py + sWo[133] * pz;
        out[(n * 3 + 2) * MDIM + m] = p2 + sWo[198] * px + sWo[199] * py + sWo[200] * pz;
    }
}

__global__ void __launch_bounds__(256, 1)
main_kernel(const float* __restrict__ prexyz,  // (2,3,4800)
            const float* __restrict__ Wout,    // (3,67)
            float* __restrict__ out)           // (2,3,4800)
{
    extern __shared__ float sm[];
    float* sS0  = sm + OFF_S0;
    float* sA1  = sm + OFF_A1;
    float* sAs  = sm + OFF_AS;
    float* sWa  = sm + OFF_WA;
    float* sWb  = sm + OFF_WB;
    float* sWs  = sm + OFF_WS;
    float* sT1b = sm + OFF_T1B;
    float* sWo  = sm + OFF_WO;
    float* sQ0  = sm + OFF_Q0;
    float* sH   = sm + OFF_H;
    float* sH1  = sm + OFF_H1;
    float* sTL  = sm + OFF_TL;

    int tid = threadIdx.x;
    for (int idx = tid; idx < NPLANE; idx += 256) {
        int nc = idx >> 6, k = idx & 63;
        sS0[nc * S0STR + k] = d_S0s[idx];
        sA1[nc * 65 + k] = d_A1s[idx];
        sAs[nc * 65 + k] = d_Ask[idx];
    }
    for (int idx = tid; idx < 4096; idx += 256) {
        sWa[idx] = d_W1aT[idx];
        sWb[idx] = d_W1bT[idx];
        sWs[idx] = d_WskT[idx];
    }
    if (tid < 64) sT1b[tid] = d_t1bv[tid];
    for (int idx = tid; idx < 201; idx += 256) sWo[idx] = Wout[idx];
    __syncthreads();

    int wid = tid >> 5, lane = tid & 31;
    int flatW = blockIdx.x * 8 + wid;          // 0..1183
    float* myH  = sH  + wid * 1024;
    float* myH1 = sH1 + wid * 1024;
    float* myQ0 = sQ0 + wid * 64;
    const int cbase = (lane & 15) * 4;
    const int kgrp  = (lane >> 4) * 4;

    // ---- 8 uniform rounds: gm = flatW + r*1184, always < 9600 ----
    float q0lo = d_q0[flatW * 64 + lane];
    float q0hi = d_q0[flatW * 64 + lane + 32];

    #pragma unroll 1
    for (int r = 0; r < 8; r++) {
        int gm = flatW + r * 1184;
        int n = gm >= MDIM;
        int m = gm - n * MDIM;
        const float* nS0 = sS0 + n * (64 * S0STR);
        const float* nA1 = sA1 + n * (64 * 65);
        const float* nAs = sAs + n * (64 * 65);

        myQ0[lane]      = q0lo;
        myQ0[lane + 32] = q0hi;
        __syncwarp();
        if (r < 7) {
            int gmn = gm + 1184;
            q0lo = d_q0[gmn * 64 + lane];      // overlaps with compute below
            q0hi = d_q0[gmn * 64 + lane + 32];
        }

        float mx[4] = {-1e30f, -1e30f, -1e30f, -1e30f};
        for (int kc = 0; kc < KDIM; kc += 8)
            chunk_body(nS0, nA1, nAs, sWa, sWb, sWs, sT1b,
                       myH, myH1, myQ0, kc, lane, cbase, kgrp, mx);

        #pragma unroll
        for (int cc = 0; cc < 4; cc++)
            mx[cc] = fmaxf(mx[cc], __shfl_xor_sync(0xffffffffu, mx[cc], 16));

        project_store(sWo, prexyz, out, mx, lane, cbase, n, m);
    }

    // ---- cooperative tail: m = 9472 + blockIdx.x (n=1), blocks 0..127 ----
    if (blockIdx.x < 128) {
        int gmt = 8 * 1184 + blockIdx.x;       // 9472..9599
        int m = gmt - MDIM;
        const float* nS0 = sS0 + 64 * S0STR;
        const float* nA1 = sA1 + 64 * 65;
        const float* nAs = sAs + 64 * 65;

        myQ0[lane]      = d_q0[gmt * 64 + lane];
        myQ0[lane + 32] = d_q0[gmt * 64 + lane + 32];
        __syncwarp();

        float mx[4] = {-1e30f, -1e30f, -1e30f, -1e30f};
        chunk_body(nS0, nA1, nAs, sWa, sWb, sWs, sT1b,
                   myH, myH1, myQ0, wid * 8, lane, cbase, kgrp, mx);

        // combine the chunk's two k-halves
        #pragma unroll
        for (int cc = 0; cc < 4; cc++)
            mx[cc] = fmaxf(mx[cc], __shfl_xor_sync(0xffffffffu, mx[cc], 16));

        // per-warp chunk maxes -> smem
        if (lane < 16) {
            #pragma unroll
            for (int cc = 0; cc < 4; cc++)
                sTL[wid * 64 + cbase + cc] = mx[cc];
        }
        __syncthreads();

        // warp 0 reduces across the 8 warps and projects
        if (wid == 0) {
            float mxr[4] = {-1e30f, -1e30f, -1e30f, -1e30f};
            if (lane < 16) {
                #pragma unroll
                for (int cc = 0; cc < 4; cc++) {
                    float v = -1e30f;
                    #pragma unroll
                    for (int w = 0; w < 8; w++)
                        v = fmaxf(v, sTL[w * 64 + cbase + cc]);
                    mxr[cc] = v;
                }
            }
            project_store(sWo, prexyz, out, mxr, lane, cbase, 1, m);
        }
    }
}

// ---------------- launcher ----------------
extern "C" void kernel_launch(void* const* d_in, const int* in_sizes, int n_in,
                              void* d_out, int out_size)
{
    const float* query = (const float*)d_in[0];
    const float* srgb  = (const float*)d_in[1];
    const float* sxyz  = (const float*)d_in[2];
    const float* prex  = (const float*)d_in[3];
    const float* maskp = (const float*)d_in[4];
    const float* W0    = (const float*)d_in[5];
    const float* g0    = (const float*)d_in[6];
    const float* b0    = (const float*)d_in[7];
    const float* m0    = (const float*)d_in[8];
    const float* v0    = (const float*)d_in[9];
    const float* W1a   = (const float*)d_in[10];
    const float* g1a   = (const float*)d_in[11];
    const float* b1a   = (const float*)d_in[12];
    const float* m1a   = (const float*)d_in[13];
    const float* v1a   = (const float*)d_in[14];
    const float* W1b   = (const float*)d_in[15];
    const float* g1b   = (const float*)d_in[16];
    const float* b1b   = (const float*)d_in[17];
    const float* m1b   = (const float*)d_in[18];
    const float* v1b   = (const float*)d_in[19];
    const float* Wsk   = (const float*)d_in[20];
    const float* Wout  = (const float*)d_in[21];
    float* out = (float*)d_out;

    // 32 blocks x 256 = exactly NPLANE entries (the round-16 bug was 64 blocks)
    prep_kernel<<<32, 256>>>(srgb, sxyz, maskp, W0,
                             g0, b0, m0, v0,
                             W1a, g1a, b1a, m1a, v1a,
                             W1b, g1b, b1b, m1b, v1b,
                             Wsk);
    q0_kernel<<<600, 256>>>(query, W0);

    const size_t smem_bytes = SMEM_FLOATS * sizeof(float);  // ~218 KB
    cudaFuncSetAttribute(main_kernel, cudaFuncAttributeMaxDynamicSharedMemorySize,
                         (int)smem_bytes);
    main_kernel<<<148, 256, smem_bytes>>>(prex, Wout, out);
}